// round 17
// baseline (speedup 1.0000x reference)
#include <cuda_runtime.h>
#include <cuda_fp16.h>
#include <math.h>

// Problem constants
#define H_    112
#define W_    200
#define HW_   (H_*W_)        // 22400
#define C_    64
#define BN_   6
#define PAD_  4
#define HP_   (H_ + 2*PAD_)  // 120
#define WP_   (W_ + 2*PAD_)  // 208
#define HPWP_ (HP_*WP_)      // 24960
#define QW_   208
#define NTAP  81

// fp16 mma, fp32 accumulate
__device__ __forceinline__ void mma_f16(float c[4], const unsigned a[4],
                                        unsigned b0, unsigned b1) {
    asm("mma.sync.aligned.m16n8k16.row.col.f32.f16.f16.f32 "
        "{%0,%1,%2,%3}, {%4,%5,%6,%7}, {%8,%9}, {%0,%1,%2,%3};"
        : "+f"(c[0]), "+f"(c[1]), "+f"(c[2]), "+f"(c[3])
        : "r"(a[0]), "r"(a[1]), "r"(a[2]), "r"(a[3]), "r"(b0), "r"(b1));
}

// ldmatrix x4 transposed b16
__device__ __forceinline__ void ldsm_x4_trans(unsigned r[4], unsigned saddr) {
    asm volatile("ldmatrix.sync.aligned.m8n8.x4.trans.shared.b16 {%0,%1,%2,%3}, [%4];"
        : "=r"(r[0]), "=r"(r[1]), "=r"(r[2]), "=r"(r[3]) : "r"(saddr));
}

__device__ __forceinline__ unsigned pack2h(float lo, float hi) {
    __half2 h = __floats2half2_rn(lo, hi);
    return *reinterpret_cast<unsigned*>(&h);
}
__device__ __forceinline__ unsigned packhh(__half lo, __half hi) {
    __half2 h = __halves2half2(lo, hi);
    return *reinterpret_cast<unsigned*>(&h);
}

// cp.async 16B (LDGSTS)
__device__ __forceinline__ void cp_async16(unsigned saddr, const void* gaddr) {
    asm volatile("cp.async.cg.shared.global [%0], [%1], 16;" :: "r"(saddr), "l"(gaddr));
}
#define CP_COMMIT() asm volatile("cp.async.commit_group;" ::: "memory")
#define CP_WAIT0()  asm volatile("cp.async.wait_group 0;" ::: "memory")

// ---------------- scratch -----------------------------------------------------
__device__ unsigned g_qh  [BN_*H_*QW_*32];   // Q fp16, [n][h][w208][ch] (u32 = 2ch)
__device__ unsigned g_kph [BN_*HPWP_*32];    // K fp16, padded channel-last
__device__ unsigned g_vph [BN_*HPWP_*32];    // V fp16, padded channel-last
__device__ uint4    g_Whf [5*4*4*32];        // fp16 weight A-frags: [l][ks][m][lane]
__device__ float    g_bf  [5*64];            // folded bias

// ---------------- prep: fine-grained, one store per thread --------------------
#define PREP_W0   10240
#define PREP_B0   10560
#define PREP_K0   133440
#define PREP_V0   256320
#define PREP_N    299328

__device__ __forceinline__ void border_px(int j, int& row, int& col) {
    if (j < 1664) {
        int r = j / 208;
        col = j - r * 208;
        row = (r < 4) ? r : (112 + r);
    } else {
        int k = j - 1664;
        row = 4 + (k >> 3);
        int c = k & 7;
        col = (c < 4) ? c : (200 + c);
    }
}

__global__ void prep_kernel(const float* __restrict__ wc, const float* __restrict__ gam,
                            const float* __restrict__ bet, const float* __restrict__ mu,
                            const float* __restrict__ var) {
    int idx = blockIdx.x * 256 + threadIdx.x;
    if (idx < PREP_W0) {
        int l    = idx >> 11;
        int r    = idx & 2047;
        int ks   = r >> 9;
        int m    = (r >> 7) & 3;
        int lane = (r >> 2) & 31;
        int j    = r & 3;
        int g  = lane >> 2;
        int tg = lane & 3;
        int o  = m*16 + g + ((j & 1) ? 8 : 0);
        int k0 = ks*16 + 2*tg + ((j >= 2) ? 8 : 0);
        float s = gam[l*64 + o] * rsqrtf(var[l*64 + o] + 1e-5f);
        float w0 = s * wc[(l*64 + o)*64 + k0];
        float w1 = s * wc[(l*64 + o)*64 + k0 + 1];
        ((unsigned*)g_Whf)[idx] = pack2h(w0, w1);
    } else if (idx < PREP_B0) {
        int i = idx - PREP_W0;
        float s = gam[i] * rsqrtf(var[i] + 1e-5f);
        g_bf[i] = bet[i] - s * mu[i];
    } else if (idx < PREP_K0) {
        int it = idx - PREP_B0;
        int pxi = it >> 3, c8 = it & 7;
        int n = pxi / 2560, j = pxi - n*2560;
        int row, col; border_px(j, row, col);
        size_t px = (size_t)(n * HP_ + row) * WP_ + col;
        ((uint4*)(g_kph + px*32))[c8] = make_uint4(0, 0, 0, 0);
    } else if (idx < PREP_V0) {
        int it = idx - PREP_K0;
        int pxi = it >> 3, c8 = it & 7;
        int n = pxi / 2560, j = pxi - n*2560;
        int row, col; border_px(j, row, col);
        size_t px = (size_t)(n * HP_ + row) * WP_ + col;
        ((uint4*)(g_vph + px*32))[c8] = make_uint4(0, 0, 0, 0);
    } else if (idx < PREP_N) {
        int it = idx - PREP_V0;
        int pxi = it >> 3, c8 = it & 7;
        int n = pxi / (H_*8);
        int rr = pxi - n*(H_*8);
        int h = rr >> 3;
        int c = rr & 7;
        size_t px = (size_t)(n*H_ + h)*QW_ + 200 + c;
        ((uint4*)(g_qh + px*32))[c8] = make_uint4(0, 0, 0, 0);
    }
}

// ---------------- fused 5-layer QKV, full fp16 tensor cores (proven R14) -----
#define XW     36
#define XBUF_U (32*XW)
#define QKV_SMEM (4*2*XBUF_U*4)

__device__ __forceinline__ void stage_tile_h(const float* __restrict__ src,
                                             unsigned* xb, int lane) {
    int q = lane >> 3;
    int p = lane & 7;
    #pragma unroll
    for (int it = 0; it < 8; it++) {
        int cp = it*4 + q;
        float4 a = *(const float4*)(src + (size_t)(2*cp)    *HW_ + p*4);
        float4 b = *(const float4*)(src + (size_t)(2*cp + 1)*HW_ + p*4);
        xb[(p*4 + 0)*XW + cp] = pack2h(a.x, b.x);
        xb[(p*4 + 1)*XW + cp] = pack2h(a.y, b.y);
        xb[(p*4 + 2)*XW + cp] = pack2h(a.z, b.z);
        xb[(p*4 + 3)*XW + cp] = pack2h(a.w, b.w);
    }
}

__device__ __forceinline__ void layer_mma_h(const unsigned* xb, int l, int lane,
                                            float c[4][4][4]) {
    int g = lane >> 2, tg = lane & 3;
    #pragma unroll
    for (int m = 0; m < 4; m++)
        #pragma unroll
        for (int nt = 0; nt < 4; nt++)
            #pragma unroll
            for (int j = 0; j < 4; j++) c[m][nt][j] = 0.f;

    const uint4* wf = g_Whf + (size_t)l*512;
    #pragma unroll
    for (int ks = 0; ks < 4; ks++) {
        uint4 a[4];
        #pragma unroll
        for (int m = 0; m < 4; m++)
            a[m] = __ldg(wf + (ks*4 + m)*32 + lane);
        #pragma unroll
        for (int nt = 0; nt < 4; nt++) {
            unsigned b0 = xb[(nt*8 + g)*XW + ks*8 + tg];
            unsigned b1 = xb[(nt*8 + g)*XW + ks*8 + tg + 4];
            #pragma unroll
            for (int m = 0; m < 4; m++)
                mma_f16(c[m][nt], (const unsigned*)&a[m], b0, b1);
        }
    }
}

__device__ __forceinline__ void epi_smem_h16(float c[4][4][4], unsigned* xbo,
                                             int l, int lane) {
    int g = lane >> 2, tg = lane & 3;
    __half* ob = (__half*)xbo;
    #pragma unroll
    for (int m = 0; m < 4; m++) {
        float b0 = g_bf[l*64 + m*16 + g];
        float b1 = g_bf[l*64 + m*16 + g + 8];
        #pragma unroll
        for (int nt = 0; nt < 4; nt++) {
            int px = nt*8 + 2*tg;
            ob[(px    )*(2*XW) + m*16 + g]     = __float2half_rn(fmaxf(c[m][nt][0] + b0, 0.f));
            ob[(px + 1)*(2*XW) + m*16 + g]     = __float2half_rn(fmaxf(c[m][nt][1] + b0, 0.f));
            ob[(px    )*(2*XW) + m*16 + g + 8] = __float2half_rn(fmaxf(c[m][nt][2] + b1, 0.f));
            ob[(px + 1)*(2*XW) + m*16 + g + 8] = __float2half_rn(fmaxf(c[m][nt][3] + b1, 0.f));
        }
    }
}

__device__ __forceinline__ void epi_gmem_h(float c[4][4][4], __half* base, int l, int lane, int px0) {
    int g = lane >> 2, tg = lane & 3;
    float bs0[4], bs1[4];
    #pragma unroll
    for (int m = 0; m < 4; m++) {
        bs0[m] = g_bf[l*64 + m*16 + g];
        bs1[m] = g_bf[l*64 + m*16 + g + 8];
    }
    #pragma unroll
    for (int nt = 0; nt < 4; nt++) {
        #pragma unroll
        for (int j = 0; j < 2; j++) {
            int px = px0 + nt*8 + 2*tg + j;
            int h = px / W_;
            int w = px - h*W_;
            __half* p = base + ((size_t)h*WP_ + w)*64;
            #pragma unroll
            for (int m = 0; m < 4; m++) {
                p[m*16 + g]     = __float2half_rn(fmaxf(c[m][nt][j]     + bs0[m], 0.f));
                p[m*16 + g + 8] = __float2half_rn(fmaxf(c[m][nt][2 + j] + bs1[m], 0.f));
            }
        }
    }
}

__global__ __launch_bounds__(128) void qkv_kernel(const float* __restrict__ img,
                                                  const float* __restrict__ wimg)
{
    extern __shared__ unsigned xs_u[];
    const int tid = threadIdx.x;
    const int wid = tid >> 5;
    const int lane = tid & 31;
    const int n = blockIdx.y;
    const int px0 = (blockIdx.x*4 + wid) * 32;

    unsigned* bufA = xs_u + wid * (2*XBUF_U);
    unsigned* bufB = bufA + XBUF_U;
    float c[4][4][4];

    const float* wsrc = wimg + (size_t)n*C_*HW_ + px0;
    const float* isrc = img  + (size_t)n*C_*HW_ + px0;
    __half* qb = (__half*)g_qh  + (size_t)n*H_*QW_*64;
    __half* kb = (__half*)g_kph + (((size_t)n*HP_ + PAD_)*WP_ + PAD_)*64;
    __half* vb = (__half*)g_vph + (((size_t)n*HP_ + PAD_)*WP_ + PAD_)*64;

    stage_tile_h(wsrc, bufA, lane);   __syncwarp();
    layer_mma_h(bufA, 4, lane, c);    epi_gmem_h(c, vb, 4, lane, px0);
    layer_mma_h(bufA, 2, lane, c);    epi_smem_h16(c, bufB, 2, lane);  __syncwarp();
    layer_mma_h(bufB, 3, lane, c);    epi_gmem_h(c, kb, 3, lane, px0);
    stage_tile_h(isrc, bufA, lane);   __syncwarp();
    layer_mma_h(bufA, 0, lane, c);    epi_smem_h16(c, bufB, 0, lane);  __syncwarp();
    layer_mma_h(bufB, 1, lane, c);    epi_gmem_h(c, qb, 1, lane, px0);
}

// ---------------- attention: fp16 everything, 3 CTAs/SM ----------------------
#define TR_   16
#define TC_   24
#define CPADH 36
#define KV2_U  (TR_*TC_*36)             // 13824 u32 = 55296 B
#define SACC_H (8*16*84)                // 10752 halves = 21504 B
#define SMEM2_BYTES (KV2_U*4 + SACC_H*2 + 8*16*4)   // 77312 B -> 3 CTAs/SM

__device__ __forceinline__ void band_store(__half* sa, float v, int px, int col, int di) {
    int dj = col - px;
    if ((unsigned)dj <= 8u)
        sa[px*84 + di*9 + dj] = __float2half_rn(v);
}

__global__ __launch_bounds__(256, 3) void attn_kernel(float* __restrict__ out)
{
    extern __shared__ unsigned kvu[];   // fp16 tile [16 rows][24 cols][36 u32]
    __half* sacc = (__half*)(kvu + KV2_U);   // [8 warps][16 px][84] fp16
    float*  sinv = (float*)(sacc + SACC_H);  // [8][16]

    const int tid  = threadIdx.x;
    const int wid  = tid >> 5;
    const int lane = tid & 31;
    const int g    = lane >> 2;
    const int tg   = lane & 3;
    const int n  = blockIdx.z;
    const int h0 = blockIdx.y * 8;
    const int w0 = blockIdx.x * 16;
    const int h  = h0 + wid;

    const unsigned kv_sbase = (unsigned)__cvta_generic_to_shared(kvu);

    // ---- stage K tile via cp.async (latency hidden behind qa loads) ----
    {
        const uint4* kb = (const uint4*)(g_kph + (size_t)(n*HP_ + h0) * WP_ * 32);
        for (int i = tid; i < TR_*TC_*8; i += 256) {
            int px = i >> 3, c8 = i & 7;
            int r = px / TC_, c = px - r*TC_;
            int pcol = w0 + c; if (pcol > 207) pcol = 207;
            cp_async16(kv_sbase + (px*CPADH + c8*4)*4,
                       kb + ((size_t)r*WP_ + pcol)*8 + c8);
        }
        CP_COMMIT();
    }

    // ---- Q fp16 A-fragments (overlaps K cp.async) ----
    unsigned qa[4][4];
    {
        const unsigned* q0 = g_qh + ((size_t)(n*H_ + h)*QW_ + (w0 + g))     * 32;
        const unsigned* q1 = g_qh + ((size_t)(n*H_ + h)*QW_ + (w0 + g + 8)) * 32;
        #pragma unroll
        for (int ks = 0; ks < 4; ks++) {
            qa[ks][0] = q0[ks*8 + tg];
            qa[ks][1] = q1[ks*8 + tg];
            qa[ks][2] = q0[ks*8 + tg + 4];
            qa[ks][3] = q1[ks*8 + tg + 4];
        }
    }
    CP_WAIT0();
    __syncthreads();

    __half* sa = sacc + wid*(16*84);

    // ---- phase 1: similarity, fp16 mma, direct band store ----
    #pragma unroll 1
    for (int di = 0; di < 9; di++) {
        float c0[3][4];
        #pragma unroll
        for (int nt = 0; nt < 3; nt++)
            #pragma unroll
            for (int j = 0; j < 4; j++) c0[nt][j] = 0.f;
        const unsigned* krow = kvu + (wid + di)*(TC_*CPADH);
        #pragma unroll
        for (int nt = 0; nt < 3; nt++) {
            const unsigned* kc = krow + (nt*8 + g)*CPADH;
            #pragma unroll
            for (int ks = 0; ks < 4; ks++) {
                unsigned b0 = kc[ks*8 + tg];
                unsigned b1 = kc[ks*8 + tg + 4];
                mma_f16(c0[nt], qa[ks], b0, b1);
            }
        }
        #pragma unroll
        for (int nt = 0; nt < 3; nt++) {
            int colb = nt*8 + 2*tg;
            band_store(sa, c0[nt][0], g,     colb,     di);
            band_store(sa, c0[nt][1], g,     colb + 1, di);
            band_store(sa, c0[nt][2], g + 8, colb,     di);
            band_store(sa, c0[nt][3], g + 8, colb + 1, di);
        }
    }
    __syncthreads();   // all warps done reading K tile

    // ---- issue V tile cp.async NOW; softmax hides the fetch latency ----
    {
        const uint4* vb = (const uint4*)(g_vph + (size_t)(n*HP_ + h0) * WP_ * 32);
        for (int i = tid; i < TR_*TC_*8; i += 256) {
            int px = i >> 3, c8 = i & 7;
            int r = px / TC_, c = px - r*TC_;
            int pcol = w0 + c; if (pcol > 207) pcol = 207;
            cp_async16(kv_sbase + (px*CPADH + c8*4)*4,
                       vb + ((size_t)r*WP_ + pcol)*8 + c8);
        }
        CP_COMMIT();
    }

    // ---- softmax (2 lanes per px) — reads/writes sacc (fp16) only ----
    {
        int px   = lane & 15;
        int half = lane >> 4;
        __half* sp = sa + px*84;
        int t0 = half * 41;
        int tc = 41 - half;
        float mx = -1e30f;
        for (int t = 0; t < tc; t++) {
            float v = __half2float(sp[t0 + t]) * 0.125f;
            mx = fmaxf(mx, v);
        }
        mx = fmaxf(mx, __shfl_xor_sync(0xffffffffu, mx, 16));
        float sum = 0.f;
        for (int t = 0; t < tc; t++) {
            float e = __expf(__half2float(sp[t0 + t]) * 0.125f - mx);
            sum += e;
            sp[t0 + t] = __float2half_rn(e);
        }
        sum += __shfl_xor_sync(0xffffffffu, sum, 16);
        if (half == 0) sinv[wid*16 + px] = 1.f / sum;
    }

    CP_WAIT0();
    __syncthreads();

    // ---- phase 2: fp16 mma, V^T via ldmatrix.x4.trans ----
    float oc[4][2][4];
    #pragma unroll
    for (int mt = 0; mt < 4; mt++)
        #pragma unroll
        for (int pxg = 0; pxg < 2; pxg++)
            #pragma unroll
            for (int j = 0; j < 4; j++) oc[mt][pxg][j] = 0.f;

    const int wl     = (lane & 7) + ((lane >> 4) << 3);   // w' row 0..15
    const int ch_off = ((lane >> 3) & 1) * 8;             // +0 or +8 halves
    const __half hz = __float2half(0.f);

    #pragma unroll 1
    for (int di = 0; di < 9; di++) {
        #pragma unroll
        for (int pxg = 0; pxg < 2; pxg++) {
            int dj0 = 2*tg - g;
            const __half* sb = sa + (pxg*8 + g)*84 + di*9;
            __half p0 = ((unsigned)(dj0)     <= 8u) ? sb[dj0]     : hz;
            __half p1 = ((unsigned)(dj0 + 1) <= 8u) ? sb[dj0 + 1] : hz;
            __half p2 = ((unsigned)(dj0 + 8) <= 8u) ? sb[dj0 + 8] : hz;
            __half p3 = ((unsigned)(dj0 + 9) <= 8u) ? sb[dj0 + 9] : hz;
            unsigned b0 = packhh(p0, p1);
            unsigned b1 = packhh(p2, p3);

            unsigned rowaddr = kv_sbase +
                ((((wid + di)*TC_ + pxg*8 + wl) * 72) + ch_off) * 2;
            #pragma unroll
            for (int mt = 0; mt < 4; mt++) {
                unsigned a[4];
                ldsm_x4_trans(a, rowaddr + mt*32);
                mma_f16(oc[mt][pxg], a, b0, b1);
            }
        }
    }

    // ---- epilogue: scale by 1/sum, store NCHW ----
    #pragma unroll
    for (int pxg = 0; pxg < 2; pxg++) {
        int pxl = pxg*8 + 2*tg;
        float is0 = sinv[wid*16 + pxl];
        float is1 = sinv[wid*16 + pxl + 1];
        int w = w0 + pxl;
        #pragma unroll
        for (int mt = 0; mt < 4; mt++) {
            int c  = mt*16 + g;
            float* ob0 = out + ((size_t)(n*C_ + c)*H_ + h)*W_;
            float* ob1 = out + ((size_t)(n*C_ + c + 8)*H_ + h)*W_;
            if (w < W_) {
                ob0[w] = oc[mt][pxg][0] * is0;
                ob1[w] = oc[mt][pxg][2] * is0;
            }
            if (w + 1 < W_) {
                ob0[w+1] = oc[mt][pxg][1] * is1;
                ob1[w+1] = oc[mt][pxg][3] * is1;
            }
        }
    }
}

// ---------------- launch ------------------------------------------------------
extern "C" void kernel_launch(void* const* d_in, const int* in_sizes, int n_in,
                              void* d_out, int out_size)
{
    (void)in_sizes; (void)n_in; (void)out_size;
    const float* img  = (const float*)d_in[0];
    const float* wimg = (const float*)d_in[1];
    const float* wc   = (const float*)d_in[2];
    const float* gg   = (const float*)d_in[3];
    const float* bb   = (const float*)d_in[4];
    const float* mm   = (const float*)d_in[5];
    const float* vv   = (const float*)d_in[6];
    float* out = (float*)d_out;

    static int attr_set = 0;
    if (!attr_set) {
        cudaFuncSetAttribute(attn_kernel,
                             cudaFuncAttributeMaxDynamicSharedMemorySize, SMEM2_BYTES);
        cudaFuncSetAttribute(qkv_kernel,
                             cudaFuncAttributeMaxDynamicSharedMemorySize, QKV_SMEM);
        attr_set = 1;
    }

    prep_kernel<<<(PREP_N + 255)/256, 256>>>(wc, gg, bb, mm, vv);

    dim3 qgrid(HW_/128, BN_);   // 175 x 6
    qkv_kernel<<<qgrid, 128, QKV_SMEM>>>(img, wimg);

    dim3 agrid((W_ + 15)/16, H_/8, BN_);   // 13 x 14 x 6
    attn_kernel<<<agrid, 256, SMEM2_BYTES>>>(out);
}